// round 14
// baseline (speedup 1.0000x reference)
#include <cuda_runtime.h>
#include <cuda_fp16.h>
#include <math.h>
#include <stdint.h>

#define Nn 100000
#define Ee 800000
#define FIN 128
#define H1  256
#define OUTD 128

// ---------------- scratch (static device globals) ----------------
__device__ __half g_Gh[(size_t)Nn * H1];   // gates pre-aggregation [N,256] fp16
__device__ __half g_Xh[(size_t)Nn * FIN];  // fp16 x
__device__ float  g_deg[Nn];
__device__ float  g_dinv[Nn];
__device__ int    g_count[Nn];
__device__ int    g_rowptr[Nn];
__device__ int    g_cursor[Nn];
__device__ int2   g_csr[Ee];               // {src, __float_as_int(dinv[src]*w)}
__device__ __half g_Wch[H1 * 256];         // folded weights [n][k] fp16, n interleaved (z,h)
__device__ float  g_bc[256];               // folded bias, interleaved
__device__ __half g_Wb0h[256 * FIN];       // fc0_w transposed [n][k] fp16
__device__ int    g_bsums[128];

// ---------------- helpers ----------------
__device__ __forceinline__ void mma_f16(float* c, const uint32_t* a, const uint32_t* b) {
    asm volatile(
        "mma.sync.aligned.m16n8k16.row.col.f32.f16.f16.f32 "
        "{%0,%1,%2,%3},{%4,%5,%6,%7},{%8,%9},{%0,%1,%2,%3};\n"
        : "+f"(c[0]), "+f"(c[1]), "+f"(c[2]), "+f"(c[3])
        : "r"(a[0]), "r"(a[1]), "r"(a[2]), "r"(a[3]), "r"(b[0]), "r"(b[1]));
}

#define LDSM_X4(r0, r1, r2, r3, addr)                                          \
    asm volatile("ldmatrix.sync.aligned.m8n8.x4.shared.b16 {%0,%1,%2,%3}, [%4];" \
                 : "=r"(r0), "=r"(r1), "=r"(r2), "=r"(r3) : "r"(addr))

__device__ __forceinline__ uint32_t smem_u32(const void* p) {
    uint32_t a;
    asm("{ .reg .u64 t; cvta.to.shared.u64 t, %1; cvt.u32.u64 %0, t; }" : "=r"(a) : "l"(p));
    return a;
}

__device__ __forceinline__ void cp_async16(uint32_t dst, const void* src, int szbytes) {
    asm volatile("cp.async.cg.shared.global [%0], [%1], 16, %2;\n"
                 :: "r"(dst), "l"(src), "r"(szbytes));
}
#define CP_COMMIT() asm volatile("cp.async.commit_group;\n" ::: "memory")
#define CP_WAIT0()  asm volatile("cp.async.wait_group 0;\n" ::: "memory")
#define CP_WAIT1()  asm volatile("cp.async.wait_group 1;\n" ::: "memory")
#define CP_WAIT2()  asm volatile("cp.async.wait_group 2;\n" ::: "memory")

// ---------------- graph prep ----------------
__global__ void k_init() {
    int i = blockIdx.x * blockDim.x + threadIdx.x;
    if (i < Nn) { g_deg[i] = 1.0f; g_count[i] = 0; g_cursor[i] = 0; }
}

__global__ void k_edge_accum(const int* __restrict__ dst, const float* __restrict__ ew) {
    int e = blockIdx.x * blockDim.x + threadIdx.x;
    if (e < Ee) {
        int d = dst[e];
        atomicAdd(&g_deg[d], ew[e]);
        atomicAdd(&g_count[d], 1);
    }
}

__global__ void k_dinv() {
    int i = blockIdx.x * blockDim.x + threadIdx.x;
    if (i < Nn) g_dinv[i] = rsqrtf(g_deg[i]);
}

__global__ void k_scan_block() {
    __shared__ int s[1024];
    int i = blockIdx.x * 1024 + threadIdx.x;
    int v = (i < Nn) ? g_count[i] : 0;
    s[threadIdx.x] = v;
    __syncthreads();
    #pragma unroll
    for (int off = 1; off < 1024; off <<= 1) {
        int t = (threadIdx.x >= off) ? s[threadIdx.x - off] : 0;
        __syncthreads();
        s[threadIdx.x] += t;
        __syncthreads();
    }
    if (i < Nn) g_rowptr[i] = s[threadIdx.x] - v;
    if (threadIdx.x == 1023) g_bsums[blockIdx.x] = s[1023];
}

__global__ void k_scan_sums(int nb) {
    if (threadIdx.x == 0 && blockIdx.x == 0) {
        int acc = 0;
        for (int b = 0; b < nb; b++) { int t = g_bsums[b]; g_bsums[b] = acc; acc += t; }
    }
}

__global__ void k_scan_add() {
    int i = blockIdx.x * 1024 + threadIdx.x;
    if (i < Nn) g_rowptr[i] += g_bsums[blockIdx.x];
}

__global__ void k_fill(const int* __restrict__ src, const int* __restrict__ dst,
                       const float* __restrict__ ew) {
    int e = blockIdx.x * blockDim.x + threadIdx.x;
    if (e < Ee) {
        int d = dst[e], s = src[e];
        int pos = g_rowptr[d] + atomicAdd(&g_cursor[d], 1);
        g_csr[pos] = make_int2(s, __float_as_int(g_dinv[s] * ew[e]));
    }
}

// ---------------- input / weight prep ----------------
// converts half2 elements [base, base+cnt) of x
__global__ void k_prep_x(const float* __restrict__ x, int base, int cnt) {
    int i = blockIdx.x * blockDim.x + threadIdx.x;
    if (i < cnt) {
        float2 v = ((const float2*)x)[base + i];
        ((__half2*)g_Xh)[base + i] = __floats2half2_rn(v.x, v.y);
    }
}

// g_Wb0h[n][k] = fp16(fc0_w[k][n])   (fc0_w is [128 k][256 n] row-major)
__global__ void k_prep_b0(const float* __restrict__ w) {
    int i = blockIdx.x * blockDim.x + threadIdx.x;
    if (i < FIN * 256) {
        int n = i >> 7, k = i & 127;
        g_Wb0h[n * FIN + k] = __float2half_rn(w[k * 256 + n]);
    }
}

// g_Wch[n][k], n interleaved (2j=z, 2j+1=h)
__global__ void k_build_wc(const float* __restrict__ czw, const float* __restrict__ chw,
                           const float* __restrict__ lzw, const float* __restrict__ lhw) {
    __shared__ float rz[128], rh[128];
    int k = blockIdx.x;        // 0..255
    int j = threadIdx.x;       // 0..127
    rz[j] = czw[k * 128 + j];
    rh[j] = chw[k * 128 + j];
    __syncthreads();
    float az = 0.f, ah = 0.f;
    #pragma unroll 4
    for (int t = 0; t < 128; t++) {
        az += rz[t] * lzw[t * 128 + j];
        ah += rh[t] * lhw[t * 128 + j];
    }
    g_Wch[(2 * j)     * 256 + k] = __float2half_rn(az);
    g_Wch[(2 * j + 1) * 256 + k] = __float2half_rn(ah);
}

__global__ void k_build_bc(const float* __restrict__ czb, const float* __restrict__ chb,
                           const float* __restrict__ lzw, const float* __restrict__ lhw,
                           const float* __restrict__ lzb, const float* __restrict__ lhb) {
    int j = threadIdx.x;
    float az = lzb[j], ah = lhb[j];
    #pragma unroll 4
    for (int t = 0; t < 128; t++) {
        az += czb[t] * lzw[t * 128 + j];
        ah += chb[t] * lhw[t * 128 + j];
    }
    g_bc[2 * j]     = az;
    g_bc[2 * j + 1] = ah;
}

// ---------------- fused double-GEMM (fp16, ldmatrix): G = relu(x@W0+b) @ Wc ----------------
// Round-12 proven stage A (fp16 g_Xh + ldmatrix); stage B upgraded to 3-stage pipeline.
#define ASA_B   0
#define ASA_SZB 5120
#define BSA_B   10240
#define BSA_SZB 20480
#define AS2_B   0
#define LDA  40
#define LDB  40
#define LDA2 264
#define BSB_B   51200
#define BSB_SZB 20480
#define SMEM_BYTES 112640

__global__ __launch_bounds__(256, 2) void k_gemm_fused(const float* __restrict__ bias0,
                                                       int rowbase, int M) {
    extern __shared__ char sm[];
    const uint32_t smb = smem_u32(sm);

    const int tid  = threadIdx.x;
    const int lane = tid & 31;
    const int w    = tid >> 5;
    const int wy   = w & 1;
    const int wx   = w >> 1;
    const int g    = lane >> 2;
    const int cq   = lane & 3;

    const int row0  = rowbase + blockIdx.x * 64;
    const int woffm = wy * 32;
    const int woffn = wx * 64;

    const uint32_t lrow_a = ((lane >> 3) & 1) * 8 + (lane & 7);
    const uint32_t lk_a   = (lane >> 4) * 8;
    const uint32_t lrow_b = (lane >> 4) * 8 + (lane & 7);
    const uint32_t lk_b   = ((lane >> 3) & 1) * 8;

    float acc[2][8][4];
    #pragma unroll
    for (int mt = 0; mt < 2; mt++)
        #pragma unroll
        for (int nt = 0; nt < 8; nt++)
            #pragma unroll
            for (int i = 0; i < 4; i++) acc[mt][nt][i] = 0.f;

    auto load_a = [&](int st, int kb) {
        {
            int r = tid >> 2, q = tid & 3;
            int gr = row0 + r;
            int ok = (gr < M);
            const __half* gp = g_Xh + (size_t)(ok ? gr : (M - 1)) * FIN + kb + q * 8;
            cp_async16(smb + ASA_B + st * ASA_SZB + (uint32_t)(r * LDA + q * 8) * 2u,
                       gp, ok ? 16 : 0);
        }
        #pragma unroll
        for (int l = 0; l < 4; l++) {
            int idx = tid + l * 256;
            int n = idx >> 2, q = idx & 3;
            cp_async16(smb + BSA_B + st * BSA_SZB + (uint32_t)(n * LDB + q * 8) * 2u,
                       g_Wb0h + (size_t)n * FIN + kb + q * 8, 16);
        }
    };

    load_a(0, 0);
    CP_COMMIT();

    for (int kbi = 0; kbi < 4; kbi++) {
        if (kbi + 1 < 4) load_a((kbi + 1) & 1, (kbi + 1) * 32);
        CP_COMMIT();
        CP_WAIT1();
        __syncthreads();
        const uint32_t abase = smb + ASA_B + (kbi & 1) * ASA_SZB
                             + ((woffm + lrow_a) * LDA + lk_a) * 2u;
        const uint32_t bbase = smb + BSA_B + (kbi & 1) * BSA_SZB
                             + ((woffn + lrow_b) * LDB + lk_b) * 2u;

        #pragma unroll
        for (int kk = 0; kk < 32; kk += 16) {
            uint32_t af[2][4], bf[8][2];
            LDSM_X4(af[0][0], af[0][1], af[0][2], af[0][3], abase + kk * 2u);
            LDSM_X4(af[1][0], af[1][1], af[1][2], af[1][3],
                    abase + (16 * LDA + kk) * 2u);
            #pragma unroll
            for (int p = 0; p < 4; p++)
                LDSM_X4(bf[2 * p][0], bf[2 * p][1], bf[2 * p + 1][0], bf[2 * p + 1][1],
                        bbase + (p * 16 * LDB + kk) * 2u);
            #pragma unroll
            for (int mt = 0; mt < 2; mt++)
                #pragma unroll
                for (int nt = 0; nt < 8; nt++)
                    mma_f16(acc[mt][nt], af[mt], bf[nt]);
        }
        __syncthreads();
    }
    CP_WAIT0();   // drain stage-A groups: clean accounting for stage B

    // preload Wc chunks 0,1 into BSB buffers 0,1 (overlap with epilogue)
    auto load_bsb = [&](int st, int kc) {
        #pragma unroll
        for (int l = 0; l < 4; l++) {
            int idx = tid + l * 256;
            int n = idx >> 2, q = idx & 3;
            cp_async16(smb + BSB_B + st * BSB_SZB + (uint32_t)(n * LDB + q * 8) * 2u,
                       g_Wch + (size_t)n * 256 + kc + q * 8, 16);
        }
    };
    load_bsb(0, 0);
    CP_COMMIT();
    load_bsb(1, 32);
    CP_COMMIT();

    // stage-A epilogue: relu + bias -> fp16 -> As2 [64][264]
    #pragma unroll
    for (int mt = 0; mt < 2; mt++) {
        int r0 = woffm + mt * 16 + g;
        int r1 = r0 + 8;
        #pragma unroll
        for (int nt = 0; nt < 8; nt++) {
            int col = woffn + nt * 8 + 2 * cq;
            float b0 = bias0[col], b1 = bias0[col + 1];
            __half2 v0 = __floats2half2_rn(fmaxf(acc[mt][nt][0] + b0, 0.f),
                                           fmaxf(acc[mt][nt][1] + b1, 0.f));
            __half2 v1 = __floats2half2_rn(fmaxf(acc[mt][nt][2] + b0, 0.f),
                                           fmaxf(acc[mt][nt][3] + b1, 0.f));
            *(__half2*)(sm + AS2_B + (r0 * LDA2 + col) * 2) = v0;
            *(__half2*)(sm + AS2_B + (r1 * LDA2 + col) * 2) = v1;
        }
    }
    __syncthreads();

    // ---- stage B: G = As2 @ Wct, K=256, 8 chunks of 32, 3-stage pipeline ----
    #pragma unroll
    for (int mt = 0; mt < 2; mt++)
        #pragma unroll
        for (int nt = 0; nt < 8; nt++)
            #pragma unroll
            for (int i = 0; i < 4; i++) acc[mt][nt][i] = 0.f;

    const uint32_t a2base = smb + AS2_B + ((woffm + lrow_a) * LDA2 + lk_a) * 2u;
    for (int it = 0; it < 8; it++) {
        if (it + 2 < 8) {
            load_bsb((it + 2) % 3, (it + 2) * 32);
            CP_COMMIT();
        }
        if (it < 6)       CP_WAIT2();
        else if (it == 6) CP_WAIT1();
        else              CP_WAIT0();
        __syncthreads();
        const uint32_t bbase = smb + BSB_B + (it % 3) * BSB_SZB
                             + ((woffn + lrow_b) * LDB + lk_b) * 2u;
        const int kg = it * 32;

        #pragma unroll
        for (int kk = 0; kk < 32; kk += 16) {
            uint32_t af[2][4], bf[8][2];
            LDSM_X4(af[0][0], af[0][1], af[0][2], af[0][3], a2base + (kg + kk) * 2u);
            LDSM_X4(af[1][0], af[1][1], af[1][2], af[1][3],
                    a2base + (16 * LDA2 + kg + kk) * 2u);
            #pragma unroll
            for (int p = 0; p < 4; p++)
                LDSM_X4(bf[2 * p][0], bf[2 * p][1], bf[2 * p + 1][0], bf[2 * p + 1][1],
                        bbase + (p * 16 * LDB + kk) * 2u);
            #pragma unroll
            for (int mt = 0; mt < 2; mt++)
                #pragma unroll
                for (int nt = 0; nt < 8; nt++)
                    mma_f16(acc[mt][nt], af[mt], bf[nt]);
        }
        __syncthreads();
    }

    // stage-B epilogue: fp16 gates to g_Gh (guarded)
    #pragma unroll
    for (int mt = 0; mt < 2; mt++) {
        int r0 = row0 + woffm + mt * 16 + g;
        int r1 = r0 + 8;
        #pragma unroll
        for (int nt = 0; nt < 8; nt++) {
            int col = woffn + nt * 8 + 2 * cq;
            if (r0 < M)
                *(__half2*)(g_Gh + (size_t)r0 * 256 + col) =
                    __floats2half2_rn(acc[mt][nt][0], acc[mt][nt][1]);
            if (r1 < M)
                *(__half2*)(g_Gh + (size_t)r1 * 256 + col) =
                    __floats2half2_rn(acc[mt][nt][2], acc[mt][nt][3]);
        }
    }
}

// ---------------- fused aggregate + bias + GRU + output head (warp-per-node, fp16 G) ----------------
__device__ __forceinline__ void acc8(float* a, uint4 u, float c) {
    float2 f0 = __half22float2(*(__half2*)&u.x);
    float2 f1 = __half22float2(*((__half2*)&u.x + 1));
    float2 f2 = __half22float2(*(__half2*)&u.z);
    float2 f3 = __half22float2(*((__half2*)&u.z + 1));
    a[0] += c * f0.x; a[1] += c * f0.y;
    a[2] += c * f1.x; a[3] += c * f1.y;
    a[4] += c * f2.x; a[5] += c * f2.y;
    a[6] += c * f3.x; a[7] += c * f3.y;
}

__global__ __launch_bounds__(256) void k_agg_gru(const float* __restrict__ fcw,
                                                 const float* __restrict__ fcb,
                                                 float* __restrict__ hout,
                                                 float* __restrict__ out) {
    const int wid  = threadIdx.x >> 5;
    const int lane = threadIdx.x & 31;
    const int n    = blockIdx.x * 8 + wid;
    if (n >= Nn) return;

    const uint4* G16 = (const uint4*)g_Gh;     // row stride 32 uint4

    float a[8];
    #pragma unroll
    for (int j = 0; j < 8; j++) a[j] = 0.f;

    const int beg = g_rowptr[n];
    const int count = g_count[n];
    const int nf = count < 32 ? count : 32;

    int2 my = make_int2(0, 0);
    if (lane < nf) my = g_csr[beg + lane];

    int e = 0;
    for (; e + 4 <= nf; e += 4) {
        int s0 = __shfl_sync(0xffffffffu, my.x, e);
        int s1 = __shfl_sync(0xffffffffu, my.x, e + 1);
        int s2 = __shfl_sync(0xffffffffu, my.x, e + 2);
        int s3 = __shfl_sync(0xffffffffu, my.x, e + 3);
        float c0 = __int_as_float(__shfl_sync(0xffffffffu, my.y, e));
        float c1 = __int_as_float(__shfl_sync(0xffffffffu, my.y, e + 1));
        float c2 = __int_as_float(__shfl_sync(0xffffffffu, my.y, e + 2));
        float c3 = __int_as_float(__shfl_sync(0xffffffffu, my.y, e + 3));
        uint4 u0 = G16[(size_t)s0 * 32 + lane];
        uint4 u1 = G16[(size_t)s1 * 32 + lane];
        uint4 u2 = G16[(size_t)s2 * 32 + lane];
        uint4 u3 = G16[(size_t)s3 * 32 + lane];
        acc8(a, u0, c0); acc8(a, u1, c1); acc8(a, u2, c2); acc8(a, u3, c3);
    }
    for (; e < nf; e++) {
        int   s = __shfl_sync(0xffffffffu, my.x, e);
        float c = __int_as_float(__shfl_sync(0xffffffffu, my.y, e));
        acc8(a, G16[(size_t)s * 32 + lane], c);
    }
    for (int ee = 32; ee < count; ee++) {      // ~never taken (Poisson(8))
        int2 p = g_csr[beg + ee];
        acc8(a, G16[(size_t)p.x * 32 + lane], __int_as_float(p.y));
    }

    const float di  = g_dinv[n];
    const float di2 = di * di;
    float s[8];
    {
        uint4 us = G16[(size_t)n * 32 + lane];
        float2 f0 = __half22float2(*(__half2*)&us.x);
        float2 f1 = __half22float2(*((__half2*)&us.x + 1));
        float2 f2 = __half22float2(*(__half2*)&us.z);
        float2 f3 = __half22float2(*((__half2*)&us.z + 1));
        s[0] = f0.x; s[1] = f0.y; s[2] = f1.x; s[3] = f1.y;
        s[4] = f2.x; s[5] = f2.y; s[6] = f3.x; s[7] = f3.y;
    }
    float4 bc0 = ((const float4*)g_bc)[2 * lane];
    float4 bc1 = ((const float4*)g_bc)[2 * lane + 1];
    float gate[8];
    gate[0] = a[0] * di + di2 * s[0] + bc0.x;
    gate[1] = a[1] * di + di2 * s[1] + bc0.y;
    gate[2] = a[2] * di + di2 * s[2] + bc0.z;
    gate[3] = a[3] * di + di2 * s[3] + bc0.w;
    gate[4] = a[4] * di + di2 * s[4] + bc1.x;
    gate[5] = a[5] * di + di2 * s[5] + bc1.y;
    gate[6] = a[6] * di + di2 * s[6] + bc1.z;
    gate[7] = a[7] * di + di2 * s[7] + bc1.w;

    float h[4];
    #pragma unroll
    for (int i = 0; i < 4; i++) {
        float z = 1.f / (1.f + expf(-gate[2 * i]));
        h[i] = (1.f - z) * tanhf(gate[2 * i + 1]);
    }

    *(float4*)(hout + (size_t)n * 128 + 4 * lane) = make_float4(h[0], h[1], h[2], h[3]);

    float4 wv = ((const float4*)fcw)[lane];
    float prod = fmaxf(h[0], 0.f) * wv.x + fmaxf(h[1], 0.f) * wv.y
               + fmaxf(h[2], 0.f) * wv.z + fmaxf(h[3], 0.f) * wv.w;
    #pragma unroll
    for (int o = 16; o; o >>= 1) prod += __shfl_xor_sync(0xffffffffu, prod, o);
    if (lane == 0) out[n] = prod + fcb[0];
}

// ---------------- launch (dual-stream fork/join, split-M prep_x overlap) ----------------
extern "C" void kernel_launch(void* const* d_in, const int* in_sizes, int n_in,
                              void* d_out, int out_size) {
    const float* x     = (const float*)d_in[0];
    const int*   ei    = (const int*)d_in[1];
    const float* ew    = (const float*)d_in[2];
    const float* fc0_w = (const float*)d_in[3];
    const float* fc0_b = (const float*)d_in[4];
    // d_in[5] = att: softmax over one element == 1.0
    const float* czw   = (const float*)d_in[6];
    const float* czb   = (const float*)d_in[7];
    const float* lzw   = (const float*)d_in[8];
    const float* lzb   = (const float*)d_in[9];
    // d_in[10..13] dead (H0 == 0 kills the R branch)
    const float* chw   = (const float*)d_in[14];
    const float* chb   = (const float*)d_in[15];
    const float* lhw   = (const float*)d_in[16];
    const float* lhb   = (const float*)d_in[17];
    const float* fcw   = (const float*)d_in[18];
    const float* fcb   = (const float*)d_in[19];

    const int* src = ei;
    const int* dst = ei + Ee;

    float* out  = (float*)d_out;
    float* hout = out + Nn;

    const int nb = (Nn + 1023) / 1024;
    const int gM   = (Nn + 63) / 64;          // 1563 blocks
    const int g0   = gM / 2;                  // 781 blocks, rows [0, 49984)
    const int g1   = gM - g0;                 // 782 blocks, rows [49984, 100000)
    const int rows0 = g0 * 64;                // 49984
    const int h2_0 = rows0 * (FIN / 2);       // half2 elems in half 0
    const int h2_1 = Nn * (FIN / 2) - h2_0;

    static cudaStream_t s1;
    static cudaEvent_t evFork, evX1, evJoin;
    static bool once = false;
    if (!once) {
        cudaFuncSetAttribute(k_gemm_fused, cudaFuncAttributeMaxDynamicSharedMemorySize, SMEM_BYTES);
        cudaStreamCreateWithFlags(&s1, cudaStreamNonBlocking);
        cudaEventCreateWithFlags(&evFork, cudaEventDisableTiming);
        cudaEventCreateWithFlags(&evX1, cudaEventDisableTiming);
        cudaEventCreateWithFlags(&evJoin, cudaEventDisableTiming);
        once = true;
    }

    // fork point: s1 work depends only on inputs
    cudaEventRecord(evFork, 0);

    // ---- default stream: weights + first half ----
    k_prep_b0<<<(FIN * 256 + 255) / 256, 256>>>(fc0_w);        // 0
    k_build_wc<<<256, 128>>>(czw, chw, lzw, lhw);              // 1
    k_prep_x<<<(h2_0 + 255) / 256, 256>>>(x, 0, h2_0);         // 2
    k_gemm_fused<<<g0, 256, SMEM_BYTES>>>(fc0_b, 0, Nn);       // 3 (ncu control)

    // ---- s1: second-half x conversion (overlaps gemm half 0), then csr chain ----
    cudaStreamWaitEvent(s1, evFork, 0);
    k_prep_x<<<(h2_1 + 255) / 256, 256, 0, s1>>>(x, h2_0, h2_1);
    cudaEventRecord(evX1, s1);
    k_init<<<(Nn + 255) / 256, 256, 0, s1>>>();
    k_edge_accum<<<(Ee + 255) / 256, 256, 0, s1>>>(dst, ew);
    k_dinv<<<(Nn + 255) / 256, 256, 0, s1>>>();
    k_scan_block<<<nb, 1024, 0, s1>>>();
    k_scan_sums<<<1, 32, 0, s1>>>(nb);
    k_scan_add<<<nb, 1024, 0, s1>>>();
    k_fill<<<(Ee + 255) / 256, 256, 0, s1>>>(src, dst, ew);
    k_build_bc<<<1, 128, 0, s1>>>(czb, chb, lzw, lhw, lzb, lhb);
    cudaEventRecord(evJoin, s1);

    // ---- default stream: second half gemm after its x data is ready ----
    cudaStreamWaitEvent(0, evX1, 0);
    k_gemm_fused<<<g1, 256, SMEM_BYTES>>>(fc0_b, rows0, Nn);

    // join: aggregation needs the full G and the csr structures
    cudaStreamWaitEvent(0, evJoin, 0);
    k_agg_gru<<<(Nn + 7) / 8, 256>>>(fcw, fcb, hout, out);
}

// round 15
// speedup vs baseline: 1.0355x; 1.0355x over previous
#include <cuda_runtime.h>
#include <cuda_fp16.h>
#include <math.h>
#include <stdint.h>

#define Nn 100000
#define Ee 800000
#define FIN 128
#define H1  256
#define OUTD 128

// ---------------- scratch (static device globals) ----------------
__device__ __half g_Gh[(size_t)Nn * H1];   // gates pre-aggregation [N,256] fp16
__device__ __half g_Xh[(size_t)Nn * FIN];  // fp16 x
__device__ float  g_deg[Nn];
__device__ float  g_dinv[Nn];
__device__ int    g_count[Nn];
__device__ int    g_rowptr[Nn];
__device__ int    g_cursor[Nn];
__device__ int2   g_csr[Ee];               // {src, __float_as_int(dinv[src]*w)}
__device__ __half g_Wch[H1 * 256];         // folded weights [n][k] fp16, n interleaved (z,h)
__device__ float  g_bc[256];               // folded bias, interleaved
__device__ __half g_Wb0h[256 * FIN];       // fc0_w transposed [n][k] fp16
__device__ int    g_bsums[128];

// ---------------- helpers ----------------
__device__ __forceinline__ void mma_f16(float* c, const uint32_t* a, const uint32_t* b) {
    asm volatile(
        "mma.sync.aligned.m16n8k16.row.col.f32.f16.f16.f32 "
        "{%0,%1,%2,%3},{%4,%5,%6,%7},{%8,%9},{%0,%1,%2,%3};\n"
        : "+f"(c[0]), "+f"(c[1]), "+f"(c[2]), "+f"(c[3])
        : "r"(a[0]), "r"(a[1]), "r"(a[2]), "r"(a[3]), "r"(b[0]), "r"(b[1]));
}

#define LDSM_X4(r0, r1, r2, r3, addr)                                          \
    asm volatile("ldmatrix.sync.aligned.m8n8.x4.shared.b16 {%0,%1,%2,%3}, [%4];" \
                 : "=r"(r0), "=r"(r1), "=r"(r2), "=r"(r3) : "r"(addr))

__device__ __forceinline__ uint32_t smem_u32(const void* p) {
    uint32_t a;
    asm("{ .reg .u64 t; cvta.to.shared.u64 t, %1; cvt.u32.u64 %0, t; }" : "=r"(a) : "l"(p));
    return a;
}

__device__ __forceinline__ void cp_async16(uint32_t dst, const void* src, int szbytes) {
    asm volatile("cp.async.cg.shared.global [%0], [%1], 16, %2;\n"
                 :: "r"(dst), "l"(src), "r"(szbytes));
}
#define CP_COMMIT() asm volatile("cp.async.commit_group;\n" ::: "memory")
#define CP_WAIT1()  asm volatile("cp.async.wait_group 1;\n" ::: "memory")

// ---------------- graph prep ----------------
__global__ void k_init() {
    int i = blockIdx.x * blockDim.x + threadIdx.x;
    if (i < Nn) { g_deg[i] = 1.0f; g_count[i] = 0; g_cursor[i] = 0; }
}

__global__ void k_edge_accum(const int* __restrict__ dst, const float* __restrict__ ew) {
    int e = blockIdx.x * blockDim.x + threadIdx.x;
    if (e < Ee) {
        int d = dst[e];
        atomicAdd(&g_deg[d], ew[e]);
        atomicAdd(&g_count[d], 1);
    }
}

__global__ void k_dinv() {
    int i = blockIdx.x * blockDim.x + threadIdx.x;
    if (i < Nn) g_dinv[i] = rsqrtf(g_deg[i]);
}

__global__ void k_scan_block() {
    __shared__ int s[1024];
    int i = blockIdx.x * 1024 + threadIdx.x;
    int v = (i < Nn) ? g_count[i] : 0;
    s[threadIdx.x] = v;
    __syncthreads();
    #pragma unroll
    for (int off = 1; off < 1024; off <<= 1) {
        int t = (threadIdx.x >= off) ? s[threadIdx.x - off] : 0;
        __syncthreads();
        s[threadIdx.x] += t;
        __syncthreads();
    }
    if (i < Nn) g_rowptr[i] = s[threadIdx.x] - v;
    if (threadIdx.x == 1023) g_bsums[blockIdx.x] = s[1023];
}

__global__ void k_scan_sums(int nb) {
    if (threadIdx.x == 0 && blockIdx.x == 0) {
        int acc = 0;
        for (int b = 0; b < nb; b++) { int t = g_bsums[b]; g_bsums[b] = acc; acc += t; }
    }
}

__global__ void k_scan_add() {
    int i = blockIdx.x * 1024 + threadIdx.x;
    if (i < Nn) g_rowptr[i] += g_bsums[blockIdx.x];
}

__global__ void k_fill(const int* __restrict__ src, const int* __restrict__ dst,
                       const float* __restrict__ ew) {
    int e = blockIdx.x * blockDim.x + threadIdx.x;
    if (e < Ee) {
        int d = dst[e], s = src[e];
        int pos = g_rowptr[d] + atomicAdd(&g_cursor[d], 1);
        g_csr[pos] = make_int2(s, __float_as_int(g_dinv[s] * ew[e]));
    }
}

// ---------------- input / weight prep ----------------
__global__ void k_prep_x(const float* __restrict__ x) {
    int i = blockIdx.x * blockDim.x + threadIdx.x;
    if (i < Nn * FIN / 2) {
        float2 v = ((const float2*)x)[i];
        ((__half2*)g_Xh)[i] = __floats2half2_rn(v.x, v.y);
    }
}

// g_Wb0h[n][k] = fp16(fc0_w[k][n])   (fc0_w is [128 k][256 n] row-major)
__global__ void k_prep_b0(const float* __restrict__ w) {
    int i = blockIdx.x * blockDim.x + threadIdx.x;
    if (i < FIN * 256) {
        int n = i >> 7, k = i & 127;
        g_Wb0h[n * FIN + k] = __float2half_rn(w[k * 256 + n]);
    }
}

// g_Wch[n][k], n interleaved (2j=z, 2j+1=h)
__global__ void k_build_wc(const float* __restrict__ czw, const float* __restrict__ chw,
                           const float* __restrict__ lzw, const float* __restrict__ lhw) {
    __shared__ float rz[128], rh[128];
    int k = blockIdx.x;        // 0..255
    int j = threadIdx.x;       // 0..127
    rz[j] = czw[k * 128 + j];
    rh[j] = chw[k * 128 + j];
    __syncthreads();
    float az = 0.f, ah = 0.f;
    #pragma unroll 4
    for (int t = 0; t < 128; t++) {
        az += rz[t] * lzw[t * 128 + j];
        ah += rh[t] * lhw[t * 128 + j];
    }
    g_Wch[(2 * j)     * 256 + k] = __float2half_rn(az);
    g_Wch[(2 * j + 1) * 256 + k] = __float2half_rn(ah);
}

__global__ void k_build_bc(const float* __restrict__ czb, const float* __restrict__ chb,
                           const float* __restrict__ lzw, const float* __restrict__ lhw,
                           const float* __restrict__ lzb, const float* __restrict__ lhb) {
    int j = threadIdx.x;
    float az = lzb[j], ah = lhb[j];
    #pragma unroll 4
    for (int t = 0; t < 128; t++) {
        az += czb[t] * lzw[t * 128 + j];
        ah += chb[t] * lhw[t * 128 + j];
    }
    g_bc[2 * j]     = az;
    g_bc[2 * j + 1] = ah;
}

// ---------------- fused double-GEMM (fp16, ldmatrix): G = relu(x@W0+b) @ Wc ----------------
// Round-12 proven configuration: 2-stage pipelines, 92 KB smem, 2 CTAs/SM.
#define ASA_B   0
#define ASA_SZB 5120
#define BSA_B   10240
#define BSA_SZB 20480
#define AS2_B   0
#define LDA  40
#define LDB  40
#define LDA2 264
#define BSB_B   51200
#define BSB_SZB 20480
#define SMEM_BYTES 92160

__global__ __launch_bounds__(256, 2) void k_gemm_fused(const float* __restrict__ bias0,
                                                       int M) {
    extern __shared__ char sm[];
    const uint32_t smb = smem_u32(sm);

    const int tid  = threadIdx.x;
    const int lane = tid & 31;
    const int w    = tid >> 5;
    const int wy   = w & 1;
    const int wx   = w >> 1;
    const int g    = lane >> 2;
    const int cq   = lane & 3;

    const int row0  = blockIdx.x * 64;
    const int woffm = wy * 32;
    const int woffn = wx * 64;

    const uint32_t lrow_a = ((lane >> 3) & 1) * 8 + (lane & 7);
    const uint32_t lk_a   = (lane >> 4) * 8;
    const uint32_t lrow_b = (lane >> 4) * 8 + (lane & 7);
    const uint32_t lk_b   = ((lane >> 3) & 1) * 8;

    float acc[2][8][4];
    #pragma unroll
    for (int mt = 0; mt < 2; mt++)
        #pragma unroll
        for (int nt = 0; nt < 8; nt++)
            #pragma unroll
            for (int i = 0; i < 4; i++) acc[mt][nt][i] = 0.f;

    auto load_a = [&](int st, int kb) {
        {
            int r = tid >> 2, q = tid & 3;
            int gr = row0 + r;
            int ok = (gr < M);
            const __half* gp = g_Xh + (size_t)(ok ? gr : (M - 1)) * FIN + kb + q * 8;
            cp_async16(smb + ASA_B + st * ASA_SZB + (uint32_t)(r * LDA + q * 8) * 2u,
                       gp, ok ? 16 : 0);
        }
        #pragma unroll
        for (int l = 0; l < 4; l++) {
            int idx = tid + l * 256;
            int n = idx >> 2, q = idx & 3;
            cp_async16(smb + BSA_B + st * BSA_SZB + (uint32_t)(n * LDB + q * 8) * 2u,
                       g_Wb0h + (size_t)n * FIN + kb + q * 8, 16);
        }
    };

    load_a(0, 0);
    CP_COMMIT();

    for (int kbi = 0; kbi < 4; kbi++) {
        if (kbi + 1 < 4) load_a((kbi + 1) & 1, (kbi + 1) * 32);
        CP_COMMIT();
        CP_WAIT1();
        __syncthreads();
        const uint32_t abase = smb + ASA_B + (kbi & 1) * ASA_SZB
                             + ((woffm + lrow_a) * LDA + lk_a) * 2u;
        const uint32_t bbase = smb + BSA_B + (kbi & 1) * BSA_SZB
                             + ((woffn + lrow_b) * LDB + lk_b) * 2u;

        #pragma unroll
        for (int kk = 0; kk < 32; kk += 16) {
            uint32_t af[2][4], bf[8][2];
            LDSM_X4(af[0][0], af[0][1], af[0][2], af[0][3], abase + kk * 2u);
            LDSM_X4(af[1][0], af[1][1], af[1][2], af[1][3],
                    abase + (16 * LDA + kk) * 2u);
            #pragma unroll
            for (int p = 0; p < 4; p++)
                LDSM_X4(bf[2 * p][0], bf[2 * p][1], bf[2 * p + 1][0], bf[2 * p + 1][1],
                        bbase + (p * 16 * LDB + kk) * 2u);
            #pragma unroll
            for (int mt = 0; mt < 2; mt++)
                #pragma unroll
                for (int nt = 0; nt < 8; nt++)
                    mma_f16(acc[mt][nt], af[mt], bf[nt]);
        }
        __syncthreads();
    }

    // start streaming Wc chunk 0 into Bsb (non-aliased) to overlap with epilogue
    {
        #pragma unroll
        for (int l = 0; l < 4; l++) {
            int idx = tid + l * 256;
            int n = idx >> 2, q = idx & 3;
            cp_async16(smb + BSB_B + (uint32_t)(n * LDB + q * 8) * 2u,
                       g_Wch + (size_t)n * 256 + q * 8, 16);
        }
        CP_COMMIT();
    }

    // stage-A epilogue: relu + bias -> fp16 -> As2 [64][264]
    #pragma unroll
    for (int mt = 0; mt < 2; mt++) {
        int r0 = woffm + mt * 16 + g;
        int r1 = r0 + 8;
        #pragma unroll
        for (int nt = 0; nt < 8; nt++) {
            int col = woffn + nt * 8 + 2 * cq;
            float b0 = bias0[col], b1 = bias0[col + 1];
            __half2 v0 = __floats2half2_rn(fmaxf(acc[mt][nt][0] + b0, 0.f),
                                           fmaxf(acc[mt][nt][1] + b1, 0.f));
            __half2 v1 = __floats2half2_rn(fmaxf(acc[mt][nt][2] + b0, 0.f),
                                           fmaxf(acc[mt][nt][3] + b1, 0.f));
            *(__half2*)(sm + AS2_B + (r0 * LDA2 + col) * 2) = v0;
            *(__half2*)(sm + AS2_B + (r1 * LDA2 + col) * 2) = v1;
        }
    }
    __syncthreads();

    // ---- stage B: G = As2 @ Wct, K=256, 8 chunks of 32 ----
    #pragma unroll
    for (int mt = 0; mt < 2; mt++)
        #pragma unroll
        for (int nt = 0; nt < 8; nt++)
            #pragma unroll
            for (int i = 0; i < 4; i++) acc[mt][nt][i] = 0.f;

    auto load_b = [&](int st, int kc) {
        #pragma unroll
        for (int l = 0; l < 4; l++) {
            int idx = tid + l * 256;
            int n = idx >> 2, q = idx & 3;
            cp_async16(smb + BSB_B + st * BSB_SZB + (uint32_t)(n * LDB + q * 8) * 2u,
                       g_Wch + (size_t)n * 256 + kc + q * 8, 16);
        }
    };

    const uint32_t a2base = smb + AS2_B + ((woffm + lrow_a) * LDA2 + lk_a) * 2u;
    for (int it = 0; it < 8; it++) {
        if (it + 1 < 8) load_b((it + 1) & 1, (it + 1) * 32);
        CP_COMMIT();
        CP_WAIT1();
        __syncthreads();
        const uint32_t bbase = smb + BSB_B + (it & 1) * BSB_SZB
                             + ((woffn + lrow_b) * LDB + lk_b) * 2u;
        const int kg = it * 32;

        #pragma unroll
        for (int kk = 0; kk < 32; kk += 16) {
            uint32_t af[2][4], bf[8][2];
            LDSM_X4(af[0][0], af[0][1], af[0][2], af[0][3], a2base + (kg + kk) * 2u);
            LDSM_X4(af[1][0], af[1][1], af[1][2], af[1][3],
                    a2base + (16 * LDA2 + kg + kk) * 2u);
            #pragma unroll
            for (int p = 0; p < 4; p++)
                LDSM_X4(bf[2 * p][0], bf[2 * p][1], bf[2 * p + 1][0], bf[2 * p + 1][1],
                        bbase + (p * 16 * LDB + kk) * 2u);
            #pragma unroll
            for (int mt = 0; mt < 2; mt++)
                #pragma unroll
                for (int nt = 0; nt < 8; nt++)
                    mma_f16(acc[mt][nt], af[mt], bf[nt]);
        }
        __syncthreads();
    }

    // stage-B epilogue: fp16 gates to g_Gh (guarded)
    #pragma unroll
    for (int mt = 0; mt < 2; mt++) {
        int r0 = row0 + woffm + mt * 16 + g;
        int r1 = r0 + 8;
        #pragma unroll
        for (int nt = 0; nt < 8; nt++) {
            int col = woffn + nt * 8 + 2 * cq;
            if (r0 < M)
                *(__half2*)(g_Gh + (size_t)r0 * 256 + col) =
                    __floats2half2_rn(acc[mt][nt][0], acc[mt][nt][1]);
            if (r1 < M)
                *(__half2*)(g_Gh + (size_t)r1 * 256 + col) =
                    __floats2half2_rn(acc[mt][nt][2], acc[mt][nt][3]);
        }
    }
}

// ---------------- fused aggregate + bias + GRU + output head (warp-per-node, fp16 G) ----------------
__device__ __forceinline__ void acc8(float* a, uint4 u, float c) {
    float2 f0 = __half22float2(*(__half2*)&u.x);
    float2 f1 = __half22float2(*((__half2*)&u.x + 1));
    float2 f2 = __half22float2(*(__half2*)&u.z);
    float2 f3 = __half22float2(*((__half2*)&u.z + 1));
    a[0] += c * f0.x; a[1] += c * f0.y;
    a[2] += c * f1.x; a[3] += c * f1.y;
    a[4] += c * f2.x; a[5] += c * f2.y;
    a[6] += c * f3.x; a[7] += c * f3.y;
}

__global__ __launch_bounds__(256) void k_agg_gru(const float* __restrict__ fcw,
                                                 const float* __restrict__ fcb,
                                                 float* __restrict__ hout,
                                                 float* __restrict__ out) {
    const int wid  = threadIdx.x >> 5;
    const int lane = threadIdx.x & 31;
    const int n    = blockIdx.x * 8 + wid;
    if (n >= Nn) return;

    const uint4* G16 = (const uint4*)g_Gh;     // row stride 32 uint4

    float a[8];
    #pragma unroll
    for (int j = 0; j < 8; j++) a[j] = 0.f;

    const int beg = g_rowptr[n];
    const int count = g_count[n];
    const int nf = count < 32 ? count : 32;

    int2 my = make_int2(0, 0);
    if (lane < nf) my = g_csr[beg + lane];

    int e = 0;
    for (; e + 4 <= nf; e += 4) {
        int s0 = __shfl_sync(0xffffffffu, my.x, e);
        int s1 = __shfl_sync(0xffffffffu, my.x, e + 1);
        int s2 = __shfl_sync(0xffffffffu, my.x, e + 2);
        int s3 = __shfl_sync(0xffffffffu, my.x, e + 3);
        float c0 = __int_as_float(__shfl_sync(0xffffffffu, my.y, e));
        float c1 = __int_as_float(__shfl_sync(0xffffffffu, my.y, e + 1));
        float c2 = __int_as_float(__shfl_sync(0xffffffffu, my.y, e + 2));
        float c3 = __int_as_float(__shfl_sync(0xffffffffu, my.y, e + 3));
        uint4 u0 = G16[(size_t)s0 * 32 + lane];
        uint4 u1 = G16[(size_t)s1 * 32 + lane];
        uint4 u2 = G16[(size_t)s2 * 32 + lane];
        uint4 u3 = G16[(size_t)s3 * 32 + lane];
        acc8(a, u0, c0); acc8(a, u1, c1); acc8(a, u2, c2); acc8(a, u3, c3);
    }
    for (; e < nf; e++) {
        int   s = __shfl_sync(0xffffffffu, my.x, e);
        float c = __int_as_float(__shfl_sync(0xffffffffu, my.y, e));
        acc8(a, G16[(size_t)s * 32 + lane], c);
    }
    for (int ee = 32; ee < count; ee++) {      // ~never taken (Poisson(8))
        int2 p = g_csr[beg + ee];
        acc8(a, G16[(size_t)p.x * 32 + lane], __int_as_float(p.y));
    }

    const float di  = g_dinv[n];
    const float di2 = di * di;
    float s[8];
    {
        uint4 us = G16[(size_t)n * 32 + lane];
        float2 f0 = __half22float2(*(__half2*)&us.x);
        float2 f1 = __half22float2(*((__half2*)&us.x + 1));
        float2 f2 = __half22float2(*(__half2*)&us.z);
        float2 f3 = __half22float2(*((__half2*)&us.z + 1));
        s[0] = f0.x; s[1] = f0.y; s[2] = f1.x; s[3] = f1.y;
        s[4] = f2.x; s[5] = f2.y; s[6] = f3.x; s[7] = f3.y;
    }
    float4 bc0 = ((const float4*)g_bc)[2 * lane];
    float4 bc1 = ((const float4*)g_bc)[2 * lane + 1];
    float gate[8];
    gate[0] = a[0] * di + di2 * s[0] + bc0.x;
    gate[1] = a[1] * di + di2 * s[1] + bc0.y;
    gate[2] = a[2] * di + di2 * s[2] + bc0.z;
    gate[3] = a[3] * di + di2 * s[3] + bc0.w;
    gate[4] = a[4] * di + di2 * s[4] + bc1.x;
    gate[5] = a[5] * di + di2 * s[5] + bc1.y;
    gate[6] = a[6] * di + di2 * s[6] + bc1.z;
    gate[7] = a[7] * di + di2 * s[7] + bc1.w;

    float h[4];
    #pragma unroll
    for (int i = 0; i < 4; i++) {
        float z = 1.f / (1.f + expf(-gate[2 * i]));
        h[i] = (1.f - z) * tanhf(gate[2 * i + 1]);
    }

    *(float4*)(hout + (size_t)n * 128 + 4 * lane) = make_float4(h[0], h[1], h[2], h[3]);

    float4 wv = ((const float4*)fcw)[lane];
    float prod = fmaxf(h[0], 0.f) * wv.x + fmaxf(h[1], 0.f) * wv.y
               + fmaxf(h[2], 0.f) * wv.z + fmaxf(h[3], 0.f) * wv.w;
    #pragma unroll
    for (int o = 16; o; o >>= 1) prod += __shfl_xor_sync(0xffffffffu, prod, o);
    if (lane == 0) out[n] = prod + fcb[0];
}

// ---------------- launch (dual-stream fork/join; weight prep overlapped with prep_x) ----------------
extern "C" void kernel_launch(void* const* d_in, const int* in_sizes, int n_in,
                              void* d_out, int out_size) {
    const float* x     = (const float*)d_in[0];
    const int*   ei    = (const int*)d_in[1];
    const float* ew    = (const float*)d_in[2];
    const float* fc0_w = (const float*)d_in[3];
    const float* fc0_b = (const float*)d_in[4];
    // d_in[5] = att: softmax over one element == 1.0
    const float* czw   = (const float*)d_in[6];
    const float* czb   = (const float*)d_in[7];
    const float* lzw   = (const float*)d_in[8];
    const float* lzb   = (const float*)d_in[9];
    // d_in[10..13] dead (H0 == 0 kills the R branch)
    const float* chw   = (const float*)d_in[14];
    const float* chb   = (const float*)d_in[15];
    const float* lhw   = (const float*)d_in[16];
    const float* lhb   = (const float*)d_in[17];
    const float* fcw   = (const float*)d_in[18];
    const float* fcb   = (const float*)d_in[19];

    const int* src = ei;
    const int* dst = ei + Ee;

    float* out  = (float*)d_out;
    float* hout = out + Nn;

    const int nb = (Nn + 1023) / 1024;
    const int gM = (Nn + 63) / 64;

    static cudaStream_t s1;
    static cudaEvent_t evFork, evW, evJoin;
    static bool once = false;
    if (!once) {
        cudaFuncSetAttribute(k_gemm_fused, cudaFuncAttributeMaxDynamicSharedMemorySize, SMEM_BYTES);
        cudaStreamCreateWithFlags(&s1, cudaStreamNonBlocking);
        cudaEventCreateWithFlags(&evFork, cudaEventDisableTiming);
        cudaEventCreateWithFlags(&evW, cudaEventDisableTiming);
        cudaEventCreateWithFlags(&evJoin, cudaEventDisableTiming);
        once = true;
    }

    // fork: s1 chain depends only on kernel inputs
    cudaEventRecord(evFork, 0);

    // ---- default stream: x conversion (12 us) ----
    k_prep_x<<<(Nn * FIN / 2 + 255) / 256, 256>>>(x);          // 0

    // ---- s1: weight prep (overlaps prep_x), then csr chain ----
    cudaStreamWaitEvent(s1, evFork, 0);
    k_prep_b0<<<(FIN * 256 + 255) / 256, 256, 0, s1>>>(fc0_w); // 1
    k_build_wc<<<256, 128, 0, s1>>>(czw, chw, lzw, lhw);       // 2
    cudaEventRecord(evW, s1);

    // ---- default stream: GEMM waits for weights; launch index 3 (ncu control) ----
    cudaStreamWaitEvent(0, evW, 0);
    k_gemm_fused<<<gM, 256, SMEM_BYTES>>>(fc0_b, Nn);          // 3

    // ---- s1: csr chain (hidden under the GEMM) ----
    k_init<<<(Nn + 255) / 256, 256, 0, s1>>>();
    k_edge_accum<<<(Ee + 255) / 256, 256, 0, s1>>>(dst, ew);
    k_dinv<<<(Nn + 255) / 256, 256, 0, s1>>>();
    k_scan_block<<<nb, 1024, 0, s1>>>();
    k_scan_sums<<<1, 32, 0, s1>>>(nb);
    k_scan_add<<<nb, 1024, 0, s1>>>();
    k_fill<<<(Ee + 255) / 256, 256, 0, s1>>>(src, dst, ew);
    k_build_bc<<<1, 128, 0, s1>>>(czb, chb, lzw, lhw, lzb, lhb);
    cudaEventRecord(evJoin, s1);

    // join: aggregation needs both the GEMM output and the csr structures
    cudaStreamWaitEvent(0, evJoin, 0);
    k_agg_gru<<<(Nn + 7) / 8, 256>>>(fcw, fcb, hout, out);
}

// round 16
// speedup vs baseline: 1.1760x; 1.1357x over previous
#include <cuda_runtime.h>
#include <cuda_fp16.h>
#include <math.h>
#include <stdint.h>

#define Nn 100000
#define Ee 800000
#define FIN 128
#define H1  256
#define OUTD 128

// ---------------- scratch (static device globals) ----------------
__device__ __half g_Gh[(size_t)Nn * H1];   // gates pre-aggregation [N,256] fp16
__device__ __half g_Xh[(size_t)Nn * FIN];  // fp16 x
__device__ float  g_deg[Nn];
__device__ float  g_dinv[Nn];
__device__ int    g_count[Nn];
__device__ int    g_rowptr[Nn];
__device__ int    g_cursor[Nn];
__device__ int2   g_csr[Ee];               // {src, __float_as_int(dinv[src]*w)}
__device__ __half g_Wch[H1 * 256];         // folded weights [n][k] fp16, n interleaved (z,h)
__device__ float  g_bc[256];               // folded bias, interleaved
__device__ __half g_Wb0h[256 * FIN];       // fc0_w transposed [n][k] fp16
__device__ int    g_bsums[128];

// ---------------- helpers ----------------
__device__ __forceinline__ void mma_f16(float* c, const uint32_t* a, const uint32_t* b) {
    asm volatile(
        "mma.sync.aligned.m16n8k16.row.col.f32.f16.f16.f32 "
        "{%0,%1,%2,%3},{%4,%5,%6,%7},{%8,%9},{%0,%1,%2,%3};\n"
        : "+f"(c[0]), "+f"(c[1]), "+f"(c[2]), "+f"(c[3])
        : "r"(a[0]), "r"(a[1]), "r"(a[2]), "r"(a[3]), "r"(b[0]), "r"(b[1]));
}

#define LDSM_X4(r0, r1, r2, r3, addr)                                          \
    asm volatile("ldmatrix.sync.aligned.m8n8.x4.shared.b16 {%0,%1,%2,%3}, [%4];" \
                 : "=r"(r0), "=r"(r1), "=r"(r2), "=r"(r3) : "r"(addr))

__device__ __forceinline__ uint32_t smem_u32(const void* p) {
    uint32_t a;
    asm("{ .reg .u64 t; cvta.to.shared.u64 t, %1; cvt.u32.u64 %0, t; }" : "=r"(a) : "l"(p));
    return a;
}

__device__ __forceinline__ void cp_async16(uint32_t dst, const void* src, int szbytes) {
    asm volatile("cp.async.cg.shared.global [%0], [%1], 16, %2;\n"
                 :: "r"(dst), "l"(src), "r"(szbytes));
}
#define CP_COMMIT() asm volatile("cp.async.commit_group;\n" ::: "memory")
#define CP_WAIT1()  asm volatile("cp.async.wait_group 1;\n" ::: "memory")

// ---------------- graph prep ----------------
__global__ void k_init() {
    int i = blockIdx.x * blockDim.x + threadIdx.x;
    if (i < Nn) { g_deg[i] = 1.0f; g_count[i] = 0; g_cursor[i] = 0; }
}

__global__ void k_edge_accum(const int* __restrict__ dst, const float* __restrict__ ew) {
    int e = blockIdx.x * blockDim.x + threadIdx.x;
    if (e < Ee) {
        int d = dst[e];
        atomicAdd(&g_deg[d], ew[e]);
        atomicAdd(&g_count[d], 1);
    }
}

__global__ void k_dinv() {
    int i = blockIdx.x * blockDim.x + threadIdx.x;
    if (i < Nn) g_dinv[i] = rsqrtf(g_deg[i]);
}

__global__ void k_scan_block() {
    __shared__ int s[1024];
    int i = blockIdx.x * 1024 + threadIdx.x;
    int v = (i < Nn) ? g_count[i] : 0;
    s[threadIdx.x] = v;
    __syncthreads();
    #pragma unroll
    for (int off = 1; off < 1024; off <<= 1) {
        int t = (threadIdx.x >= off) ? s[threadIdx.x - off] : 0;
        __syncthreads();
        s[threadIdx.x] += t;
        __syncthreads();
    }
    if (i < Nn) g_rowptr[i] = s[threadIdx.x] - v;
    if (threadIdx.x == 1023) g_bsums[blockIdx.x] = s[1023];
}

__global__ void k_scan_sums(int nb) {
    if (threadIdx.x == 0 && blockIdx.x == 0) {
        int acc = 0;
        for (int b = 0; b < nb; b++) { int t = g_bsums[b]; g_bsums[b] = acc; acc += t; }
    }
}

__global__ void k_scan_add() {
    int i = blockIdx.x * 1024 + threadIdx.x;
    if (i < Nn) g_rowptr[i] += g_bsums[blockIdx.x];
}

__global__ void k_fill(const int* __restrict__ src, const int* __restrict__ dst,
                       const float* __restrict__ ew) {
    int e = blockIdx.x * blockDim.x + threadIdx.x;
    if (e < Ee) {
        int d = dst[e], s = src[e];
        int pos = g_rowptr[d] + atomicAdd(&g_cursor[d], 1);
        g_csr[pos] = make_int2(s, __float_as_int(g_dinv[s] * ew[e]));
    }
}

// ---------------- input / weight prep ----------------
// float4-vectorized x -> fp16 conversion (3.2M float4 over the grid)
__global__ void k_prep_x(const float* __restrict__ x) {
    int i = blockIdx.x * blockDim.x + threadIdx.x;
    if (i < Nn * FIN / 4) {
        float4 v = ((const float4*)x)[i];
        __half2 h0 = __floats2half2_rn(v.x, v.y);
        __half2 h1 = __floats2half2_rn(v.z, v.w);
        ((uint2*)g_Xh)[i] = make_uint2(*(uint32_t*)&h0, *(uint32_t*)&h1);
    }
}

// g_Wb0h[n][k] = fp16(fc0_w[k][n])   (fc0_w is [128 k][256 n] row-major)
__global__ void k_prep_b0(const float* __restrict__ w) {
    int i = blockIdx.x * blockDim.x + threadIdx.x;
    if (i < FIN * 256) {
        int n = i >> 7, k = i & 127;
        g_Wb0h[n * FIN + k] = __float2half_rn(w[k * 256 + n]);
    }
}

// g_Wch[n][k], n interleaved (2j=z, 2j+1=h)
__global__ void k_build_wc(const float* __restrict__ czw, const float* __restrict__ chw,
                           const float* __restrict__ lzw, const float* __restrict__ lhw) {
    __shared__ float rz[128], rh[128];
    int k = blockIdx.x;        // 0..255
    int j = threadIdx.x;       // 0..127
    rz[j] = czw[k * 128 + j];
    rh[j] = chw[k * 128 + j];
    __syncthreads();
    float az = 0.f, ah = 0.f;
    #pragma unroll 4
    for (int t = 0; t < 128; t++) {
        az += rz[t] * lzw[t * 128 + j];
        ah += rh[t] * lhw[t * 128 + j];
    }
    g_Wch[(2 * j)     * 256 + k] = __float2half_rn(az);
    g_Wch[(2 * j + 1) * 256 + k] = __float2half_rn(ah);
}

__global__ void k_build_bc(const float* __restrict__ czb, const float* __restrict__ chb,
                           const float* __restrict__ lzw, const float* __restrict__ lhw,
                           const float* __restrict__ lzb, const float* __restrict__ lhb) {
    int j = threadIdx.x;
    float az = lzb[j], ah = lhb[j];
    #pragma unroll 4
    for (int t = 0; t < 128; t++) {
        az += czb[t] * lzw[t * 128 + j];
        ah += chb[t] * lhw[t * 128 + j];
    }
    g_bc[2 * j]     = az;
    g_bc[2 * j + 1] = ah;
}

// ---------------- fused double-GEMM (fp16, ldmatrix): G = relu(x@W0+b) @ Wc ----------------
// Round-12 proven configuration: 2-stage pipelines, 92 KB smem, 2 CTAs/SM.
#define ASA_B   0
#define ASA_SZB 5120
#define BSA_B   10240
#define BSA_SZB 20480
#define AS2_B   0
#define LDA  40
#define LDB  40
#define LDA2 264
#define BSB_B   51200
#define BSB_SZB 20480
#define SMEM_BYTES 92160

__global__ __launch_bounds__(256, 2) void k_gemm_fused(const float* __restrict__ bias0,
                                                       int M) {
    extern __shared__ char sm[];
    const uint32_t smb = smem_u32(sm);

    const int tid  = threadIdx.x;
    const int lane = tid & 31;
    const int w    = tid >> 5;
    const int wy   = w & 1;
    const int wx   = w >> 1;
    const int g    = lane >> 2;
    const int cq   = lane & 3;

    const int row0  = blockIdx.x * 64;
    const int woffm = wy * 32;
    const int woffn = wx * 64;

    const uint32_t lrow_a = ((lane >> 3) & 1) * 8 + (lane & 7);
    const uint32_t lk_a   = (lane >> 4) * 8;
    const uint32_t lrow_b = (lane >> 4) * 8 + (lane & 7);
    const uint32_t lk_b   = ((lane >> 3) & 1) * 8;

    float acc[2][8][4];
    #pragma unroll
    for (int mt = 0; mt < 2; mt++)
        #pragma unroll
        for (int nt = 0; nt < 8; nt++)
            #pragma unroll
            for (int i = 0; i < 4; i++) acc[mt][nt][i] = 0.f;

    auto load_a = [&](int st, int kb) {
        {
            int r = tid >> 2, q = tid & 3;
            int gr = row0 + r;
            int ok = (gr < M);
            const __half* gp = g_Xh + (size_t)(ok ? gr : (M - 1)) * FIN + kb + q * 8;
            cp_async16(smb + ASA_B + st * ASA_SZB + (uint32_t)(r * LDA + q * 8) * 2u,
                       gp, ok ? 16 : 0);
        }
        #pragma unroll
        for (int l = 0; l < 4; l++) {
            int idx = tid + l * 256;
            int n = idx >> 2, q = idx & 3;
            cp_async16(smb + BSA_B + st * BSA_SZB + (uint32_t)(n * LDB + q * 8) * 2u,
                       g_Wb0h + (size_t)n * FIN + kb + q * 8, 16);
        }
    };

    load_a(0, 0);
    CP_COMMIT();

    for (int kbi = 0; kbi < 4; kbi++) {
        if (kbi + 1 < 4) load_a((kbi + 1) & 1, (kbi + 1) * 32);
        CP_COMMIT();
        CP_WAIT1();
        __syncthreads();
        const uint32_t abase = smb + ASA_B + (kbi & 1) * ASA_SZB
                             + ((woffm + lrow_a) * LDA + lk_a) * 2u;
        const uint32_t bbase = smb + BSA_B + (kbi & 1) * BSA_SZB
                             + ((woffn + lrow_b) * LDB + lk_b) * 2u;

        #pragma unroll
        for (int kk = 0; kk < 32; kk += 16) {
            uint32_t af[2][4], bf[8][2];
            LDSM_X4(af[0][0], af[0][1], af[0][2], af[0][3], abase + kk * 2u);
            LDSM_X4(af[1][0], af[1][1], af[1][2], af[1][3],
                    abase + (16 * LDA + kk) * 2u);
            #pragma unroll
            for (int p = 0; p < 4; p++)
                LDSM_X4(bf[2 * p][0], bf[2 * p][1], bf[2 * p + 1][0], bf[2 * p + 1][1],
                        bbase + (p * 16 * LDB + kk) * 2u);
            #pragma unroll
            for (int mt = 0; mt < 2; mt++)
                #pragma unroll
                for (int nt = 0; nt < 8; nt++)
                    mma_f16(acc[mt][nt], af[mt], bf[nt]);
        }
        __syncthreads();
    }

    // start streaming Wc chunk 0 into Bsb (non-aliased) to overlap with epilogue
    {
        #pragma unroll
        for (int l = 0; l < 4; l++) {
            int idx = tid + l * 256;
            int n = idx >> 2, q = idx & 3;
            cp_async16(smb + BSB_B + (uint32_t)(n * LDB + q * 8) * 2u,
                       g_Wch + (size_t)n * 256 + q * 8, 16);
        }
        CP_COMMIT();
    }

    // stage-A epilogue: relu + bias -> fp16 -> As2 [64][264]
    #pragma unroll
    for (int mt = 0; mt < 2; mt++) {
        int r0 = woffm + mt * 16 + g;
        int r1 = r0 + 8;
        #pragma unroll
        for (int nt = 0; nt < 8; nt++) {
            int col = woffn + nt * 8 + 2 * cq;
            float b0 = bias0[col], b1 = bias0[col + 1];
            __half2 v0 = __floats2half2_rn(fmaxf(acc[mt][nt][0] + b0, 0.f),
                                           fmaxf(acc[mt][nt][1] + b1, 0.f));
            __half2 v1 = __floats2half2_rn(fmaxf(acc[mt][nt][2] + b0, 0.f),
                                           fmaxf(acc[mt][nt][3] + b1, 0.f));
            *(__half2*)(sm + AS2_B + (r0 * LDA2 + col) * 2) = v0;
            *(__half2*)(sm + AS2_B + (r1 * LDA2 + col) * 2) = v1;
        }
    }
    __syncthreads();

    // ---- stage B: G = As2 @ Wct, K=256, 8 chunks of 32 ----
    #pragma unroll
    for (int mt = 0; mt < 2; mt++)
        #pragma unroll
        for (int nt = 0; nt < 8; nt++)
            #pragma unroll
            for (int i = 0; i < 4; i++) acc[mt][nt][i] = 0.f;

    auto load_b = [&](int st, int kc) {
        #pragma unroll
        for (int l = 0; l < 4; l++) {
            int idx = tid + l * 256;
            int n = idx >> 2, q = idx & 3;
            cp_async16(smb + BSB_B + st * BSB_SZB + (uint32_t)(n * LDB + q * 8) * 2u,
                       g_Wch + (size_t)n * 256 + kc + q * 8, 16);
        }
    };

    const uint32_t a2base = smb + AS2_B + ((woffm + lrow_a) * LDA2 + lk_a) * 2u;
    for (int it = 0; it < 8; it++) {
        if (it + 1 < 8) load_b((it + 1) & 1, (it + 1) * 32);
        CP_COMMIT();
        CP_WAIT1();
        __syncthreads();
        const uint32_t bbase = smb + BSB_B + (it & 1) * BSB_SZB
                             + ((woffn + lrow_b) * LDB + lk_b) * 2u;
        const int kg = it * 32;

        #pragma unroll
        for (int kk = 0; kk < 32; kk += 16) {
            uint32_t af[2][4], bf[8][2];
            LDSM_X4(af[0][0], af[0][1], af[0][2], af[0][3], a2base + (kg + kk) * 2u);
            LDSM_X4(af[1][0], af[1][1], af[1][2], af[1][3],
                    a2base + (16 * LDA2 + kg + kk) * 2u);
            #pragma unroll
            for (int p = 0; p < 4; p++)
                LDSM_X4(bf[2 * p][0], bf[2 * p][1], bf[2 * p + 1][0], bf[2 * p + 1][1],
                        bbase + (p * 16 * LDB + kk) * 2u);
            #pragma unroll
            for (int mt = 0; mt < 2; mt++)
                #pragma unroll
                for (int nt = 0; nt < 8; nt++)
                    mma_f16(acc[mt][nt], af[mt], bf[nt]);
        }
        __syncthreads();
    }

    // stage-B epilogue: fp16 gates to g_Gh (guarded)
    #pragma unroll
    for (int mt = 0; mt < 2; mt++) {
        int r0 = row0 + woffm + mt * 16 + g;
        int r1 = r0 + 8;
        #pragma unroll
        for (int nt = 0; nt < 8; nt++) {
            int col = woffn + nt * 8 + 2 * cq;
            if (r0 < M)
                *(__half2*)(g_Gh + (size_t)r0 * 256 + col) =
                    __floats2half2_rn(acc[mt][nt][0], acc[mt][nt][1]);
            if (r1 < M)
                *(__half2*)(g_Gh + (size_t)r1 * 256 + col) =
                    __floats2half2_rn(acc[mt][nt][2], acc[mt][nt][3]);
        }
    }
}

// ---------------- fused aggregate + bias + GRU + output head (warp-per-node, fp16 G) ----------------
__device__ __forceinline__ void acc8(float* a, uint4 u, float c) {
    float2 f0 = __half22float2(*(__half2*)&u.x);
    float2 f1 = __half22float2(*((__half2*)&u.x + 1));
    float2 f2 = __half22float2(*(__half2*)&u.z);
    float2 f3 = __half22float2(*((__half2*)&u.z + 1));
    a[0] += c * f0.x; a[1] += c * f0.y;
    a[2] += c * f1.x; a[3] += c * f1.y;
    a[4] += c * f2.x; a[5] += c * f2.y;
    a[6] += c * f3.x; a[7] += c * f3.y;
}

__global__ __launch_bounds__(256) void k_agg_gru(const float* __restrict__ fcw,
                                                 const float* __restrict__ fcb,
                                                 float* __restrict__ hout,
                                                 float* __restrict__ out) {
    const int wid  = threadIdx.x >> 5;
    const int lane = threadIdx.x & 31;
    const int n    = blockIdx.x * 8 + wid;
    if (n >= Nn) return;

    const uint4* G16 = (const uint4*)g_Gh;     // row stride 32 uint4

    float a[8];
    #pragma unroll
    for (int j = 0; j < 8; j++) a[j] = 0.f;

    const int beg = g_rowptr[n];
    const int count = g_count[n];
    const int nf = count < 32 ? count : 32;

    int2 my = make_int2(0, 0);
    if (lane < nf) my = g_csr[beg + lane];

    int e = 0;
    for (; e + 4 <= nf; e += 4) {
        int s0 = __shfl_sync(0xffffffffu, my.x, e);
        int s1 = __shfl_sync(0xffffffffu, my.x, e + 1);
        int s2 = __shfl_sync(0xffffffffu, my.x, e + 2);
        int s3 = __shfl_sync(0xffffffffu, my.x, e + 3);
        float c0 = __int_as_float(__shfl_sync(0xffffffffu, my.y, e));
        float c1 = __int_as_float(__shfl_sync(0xffffffffu, my.y, e + 1));
        float c2 = __int_as_float(__shfl_sync(0xffffffffu, my.y, e + 2));
        float c3 = __int_as_float(__shfl_sync(0xffffffffu, my.y, e + 3));
        uint4 u0 = G16[(size_t)s0 * 32 + lane];
        uint4 u1 = G16[(size_t)s1 * 32 + lane];
        uint4 u2 = G16[(size_t)s2 * 32 + lane];
        uint4 u3 = G16[(size_t)s3 * 32 + lane];
        acc8(a, u0, c0); acc8(a, u1, c1); acc8(a, u2, c2); acc8(a, u3, c3);
    }
    for (; e < nf; e++) {
        int   s = __shfl_sync(0xffffffffu, my.x, e);
        float c = __int_as_float(__shfl_sync(0xffffffffu, my.y, e));
        acc8(a, G16[(size_t)s * 32 + lane], c);
    }
    for (int ee = 32; ee < count; ee++) {      // ~never taken (Poisson(8))
        int2 p = g_csr[beg + ee];
        acc8(a, G16[(size_t)p.x * 32 + lane], __int_as_float(p.y));
    }

    const float di  = g_dinv[n];
    const float di2 = di * di;
    float s[8];
    {
        uint4 us = G16[(size_t)n * 32 + lane];
        float2 f0 = __half22float2(*(__half2*)&us.x);
        float2 f1 = __half22float2(*((__half2*)&us.x + 1));
        float2 f2 = __half22float2(*(__half2*)&us.z);
        float2 f3 = __half22float2(*((__half2*)&us.z + 1));
        s[0] = f0.x; s[1] = f0.y; s[2] = f1.x; s[3] = f1.y;
        s[4] = f2.x; s[5] = f2.y; s[6] = f3.x; s[7] = f3.y;
    }
    float4 bc0 = ((const float4*)g_bc)[2 * lane];
    float4 bc1 = ((const float4*)g_bc)[2 * lane + 1];
    float gate[8];
    gate[0] = a[0] * di + di2 * s[0] + bc0.x;
    gate[1] = a[1] * di + di2 * s[1] + bc0.y;
    gate[2] = a[2] * di + di2 * s[2] + bc0.z;
    gate[3] = a[3] * di + di2 * s[3] + bc0.w;
    gate[4] = a[4] * di + di2 * s[4] + bc1.x;
    gate[5] = a[5] * di + di2 * s[5] + bc1.y;
    gate[6] = a[6] * di + di2 * s[6] + bc1.z;
    gate[7] = a[7] * di + di2 * s[7] + bc1.w;

    float h[4];
    #pragma unroll
    for (int i = 0; i < 4; i++) {
        float z = 1.f / (1.f + expf(-gate[2 * i]));
        h[i] = (1.f - z) * tanhf(gate[2 * i + 1]);
    }

    *(float4*)(hout + (size_t)n * 128 + 4 * lane) = make_float4(h[0], h[1], h[2], h[3]);

    float4 wv = ((const float4*)fcw)[lane];
    float prod = fmaxf(h[0], 0.f) * wv.x + fmaxf(h[1], 0.f) * wv.y
               + fmaxf(h[2], 0.f) * wv.z + fmaxf(h[3], 0.f) * wv.w;
    #pragma unroll
    for (int o = 16; o; o >>= 1) prod += __shfl_xor_sync(0xffffffffu, prod, o);
    if (lane == 0) out[n] = prod + fcb[0];
}

// ---------------- launch (round-12 proven dual-stream topology) ----------------
extern "C" void kernel_launch(void* const* d_in, const int* in_sizes, int n_in,
                              void* d_out, int out_size) {
    const float* x     = (const float*)d_in[0];
    const int*   ei    = (const int*)d_in[1];
    const float* ew    = (const float*)d_in[2];
    const float* fc0_w = (const float*)d_in[3];
    const float* fc0_b = (const float*)d_in[4];
    // d_in[5] = att: softmax over one element == 1.0
    const float* czw   = (const float*)d_in[6];
    const float* czb   = (const float*)d_in[7];
    const float* lzw   = (const float*)d_in[8];
    const float* lzb   = (const float*)d_in[9];
    // d_in[10..13] dead (H0 == 0 kills the R branch)
    const float* chw   = (const float*)d_in[14];
    const float* chb   = (const float*)d_in[15];
    const float* lhw   = (const float*)d_in[16];
    const float* lhb   = (const float*)d_in[17];
    const float* fcw   = (const float*)d_in[18];
    const float* fcb   = (const float*)d_in[19];

    const int* src = ei;
    const int* dst = ei + Ee;

    float* out  = (float*)d_out;
    float* hout = out + Nn;

    const int nb = (Nn + 1023) / 1024;
    const int gM = (Nn + 63) / 64;

    static cudaStream_t s1;
    static cudaEvent_t evFork, evJoin;
    static bool once = false;
    if (!once) {
        cudaFuncSetAttribute(k_gemm_fused, cudaFuncAttributeMaxDynamicSharedMemorySize, SMEM_BYTES);
        cudaStreamCreateWithFlags(&s1, cudaStreamNonBlocking);
        cudaEventCreateWithFlags(&evFork, cudaEventDisableTiming);
        cudaEventCreateWithFlags(&evJoin, cudaEventDisableTiming);
        once = true;
    }

    // fork point: csr chain (s1) is independent of the GEMM chain (default stream)
    cudaEventRecord(evFork, 0);

    // ---- GEMM chain on the capture (default) stream; gemm = kernel-launch index 3 ----
    k_prep_x<<<(Nn * FIN / 4 + 255) / 256, 256>>>(x);          // 0
    k_prep_b0<<<(FIN * 256 + 255) / 256, 256>>>(fc0_w);        // 1
    k_build_wc<<<256, 128>>>(czw, chw, lzw, lhw);              // 2

    k_gemm_fused<<<gM, 256, SMEM_BYTES>>>(fc0_b, Nn);          // 3 (ncu control)

    // ---- csr chain on s1, depends only on the fork event ----
    cudaStreamWaitEvent(s1, evFork, 0);
    k_init<<<(Nn + 255) / 256, 256, 0, s1>>>();
    k_edge_accum<<<(Ee + 255) / 256, 256, 0, s1>>>(dst, ew);
    k_dinv<<<(Nn + 255) / 256, 256, 0, s1>>>();
    k_scan_block<<<nb, 1024, 0, s1>>>();
    k_scan_sums<<<1, 32, 0, s1>>>(nb);
    k_scan_add<<<nb, 1024, 0, s1>>>();
    k_fill<<<(Ee + 255) / 256, 256, 0, s1>>>(src, dst, ew);
    k_build_bc<<<1, 128, 0, s1>>>(czb, chb, lzw, lhw, lzb, lhb);
    cudaEventRecord(evJoin, s1);

    // join: aggregation needs both the GEMM output and the csr structures
    cudaStreamWaitEvent(0, evJoin, 0);
    k_agg_gru<<<(Nn + 7) / 8, 256>>>(fcw, fcb, hout, out);
}